// round 5
// baseline (speedup 1.0000x reference)
#include <cuda_runtime.h>
#include <cstdint>

// Problem shape (GCNConv: N=10000 nodes, E=160000 edges, D_in=D_out=512)
#define MAX_N 10000
#define D     512
#define D4    128   // D/4 float4 per row

// ---------------- device scratch (no allocations allowed) ----------------
__device__ float g_h[(size_t)MAX_N * D];   // h = x @ W   (20 MB)
__device__ float g_deg[MAX_N];
__device__ float g_dinv[MAX_N];

// ---------------- degree / normalization ----------------
__global__ void k_deg_init(int n) {
    int i = blockIdx.x * blockDim.x + threadIdx.x;
    if (i < n) g_deg[i] = 1.0f;            // self-loop weight
}

__global__ void k_deg_acc(const int* __restrict__ ei,
                          const float* __restrict__ ew, int E) {
    int e = blockIdx.x * blockDim.x + threadIdx.x;
    if (e < E) {
        int c = ei[E + e];                 // target node (row 1 of edge_index)
        atomicAdd(&g_deg[c], ew[e]);
    }
}

__global__ void k_dinv(int n) {
    int i = blockIdx.x * blockDim.x + threadIdx.x;
    if (i < n) {
        float d = g_deg[i];
        g_dinv[i] = (d > 0.0f) ? rsqrtf(d) : 0.0f;
    }
}

// ---------------- fp32 SIMT GEMM: h = x(MxK) @ W(KxN) ----------------
#define BM 128
#define BN 128
#define BK 8
#define TM 8
#define TN 8

__global__ __launch_bounds__(256)
void k_gemm(const float* __restrict__ A, const float* __restrict__ B,
            float* __restrict__ C, int M, int Nn, int K) {
    __shared__ float As[BK][BM];
    __shared__ float Bs[BK][BN];

    const int tid = threadIdx.x;
    const int tx = tid & 15;          // 0..15 (N dir)
    const int ty = tid >> 4;          // 0..15 (M dir)
    const int m0 = blockIdx.y * BM;
    const int n0 = blockIdx.x * BN;

    // A-tile load mapping: 128 rows x 8 k, one float4 per thread
    const int a_row = tid >> 1;           // 0..127
    const int a_kq  = (tid & 1) * 4;      // 0 or 4
    // B-tile load mapping: 8 k x 128 n, one float4 per thread
    const int b_k = tid >> 5;             // 0..7
    const int b_n = (tid & 31) * 4;       // 0..124

    float acc[TM][TN];
    #pragma unroll
    for (int i = 0; i < TM; i++)
        #pragma unroll
        for (int j = 0; j < TN; j++) acc[i][j] = 0.0f;

    for (int k0 = 0; k0 < K; k0 += BK) {
        // A: transpose into As[k][m]
        int gr = m0 + a_row;
        float4 av = make_float4(0.f, 0.f, 0.f, 0.f);
        if (gr < M) av = *(const float4*)(A + (size_t)gr * K + k0 + a_kq);
        As[a_kq + 0][a_row] = av.x;
        As[a_kq + 1][a_row] = av.y;
        As[a_kq + 2][a_row] = av.z;
        As[a_kq + 3][a_row] = av.w;
        // B: natural layout
        *(float4*)&Bs[b_k][b_n] =
            *(const float4*)(B + (size_t)(k0 + b_k) * Nn + n0 + b_n);
        __syncthreads();

        #pragma unroll
        for (int k = 0; k < BK; k++) {
            float a[TM], b[TN];
            *(float4*)&a[0] = *(const float4*)&As[k][ty * TM];
            *(float4*)&a[4] = *(const float4*)&As[k][ty * TM + 4];
            *(float4*)&b[0] = *(const float4*)&Bs[k][tx * TN];
            *(float4*)&b[4] = *(const float4*)&Bs[k][tx * TN + 4];
            #pragma unroll
            for (int i = 0; i < TM; i++)
                #pragma unroll
                for (int j = 0; j < TN; j++)
                    acc[i][j] = fmaf(a[i], b[j], acc[i][j]);
        }
        __syncthreads();
    }

    #pragma unroll
    for (int i = 0; i < TM; i++) {
        int gr = m0 + ty * TM + i;
        if (gr < M) {
            float4* cp = (float4*)(C + (size_t)gr * Nn + n0 + tx * TN);
            cp[0] = make_float4(acc[i][0], acc[i][1], acc[i][2], acc[i][3]);
            cp[1] = make_float4(acc[i][4], acc[i][5], acc[i][6], acc[i][7]);
        }
    }
}

// ---------------- epilogue init: out = b + h * dinv^2 (self-loop) ----------------
__global__ void k_out_init(const float* __restrict__ bias,
                           float* __restrict__ out, int total4) {
    int t = blockIdx.x * blockDim.x + threadIdx.x;
    if (t >= total4) return;
    int n = t >> 7;           // /128 (float4s per row)
    int q = t & 127;
    float s = g_dinv[n];
    s = s * s;
    float4 hv = ((const float4*)g_h)[t];
    float4 bv = ((const float4*)bias)[q];
    float4 o;
    o.x = bv.x + hv.x * s;
    o.y = bv.y + hv.y * s;
    o.z = bv.z + hv.z * s;
    o.w = bv.w + hv.w * s;
    ((float4*)out)[t] = o;
}

// ---------------- edge scatter: one warp per edge, vector reduces ----------------
__global__ __launch_bounds__(256)
void k_scatter(const int* __restrict__ ei, const float* __restrict__ ew,
               float* __restrict__ out, int E) {
    int w = (int)((blockIdx.x * blockDim.x + threadIdx.x) >> 5);
    int lane = threadIdx.x & 31;
    if (w >= E) return;

    int r = ei[w];        // source node (row 0)
    int c = ei[E + w];    // target node (row 1)
    float nrm = g_dinv[r] * ew[w] * g_dinv[c];

    const float4* hp = (const float4*)g_h + (size_t)r * D4;
    float4* op = (float4*)out + (size_t)c * D4;

    #pragma unroll
    for (int i = 0; i < 4; i++) {
        int idx = lane + i * 32;
        float4 v = hp[idx];
        v.x *= nrm; v.y *= nrm; v.z *= nrm; v.w *= nrm;
        asm volatile("red.global.add.v4.f32 [%0], {%1,%2,%3,%4};"
                     :: "l"(op + idx), "f"(v.x), "f"(v.y), "f"(v.z), "f"(v.w)
                     : "memory");
    }
}

// ---------------- launch ----------------
extern "C" void kernel_launch(void* const* d_in, const int* in_sizes, int n_in,
                              void* d_out, int out_size) {
    const float* x  = (const float*)d_in[0];       // [N, 512] fp32
    const int*   ei = (const int*)d_in[1];         // [2, E] int32 (jax x64 off)
    const float* ew = (const float*)d_in[2];       // [E]
    const float* W  = (const float*)d_in[3];       // [512, 512]
    const float* b  = (const float*)d_in[4];       // [512]
    float* out = (float*)d_out;

    const int N = in_sizes[0] / D;   // 10000
    const int E = in_sizes[2];       // 160000

    float* h;
    cudaGetSymbolAddress((void**)&h, g_h);

    // 1) degree + dinv
    k_deg_init<<<(N + 255) / 256, 256>>>(N);
    k_deg_acc<<<(E + 255) / 256, 256>>>(ei, ew, E);
    k_dinv<<<(N + 255) / 256, 256>>>(N);

    // 2) h = x @ W
    dim3 grid((D + BN - 1) / BN, (N + BM - 1) / BM);
    k_gemm<<<grid, 256>>>(x, W, h, N, D, D);

    // 3) out = b + h * dinv^2   (self-loop + bias, initializes all of d_out)
    int total4 = N * D4;
    k_out_init<<<(total4 + 255) / 256, 256>>>(b, out, total4);

    // 4) edge scatter with vector global reduces
    int blocks = (E * 32 + 255) / 256;
    k_scatter<<<blocks, 256>>>(ei, ew, out, E);
}

// round 7
// speedup vs baseline: 2.0148x; 2.0148x over previous
#include <cuda_runtime.h>
#include <cstdint>

// GCNConv: N=10000 nodes, E=160000 edges, D_in=D_out=512
#define MAX_N 10000
#define D     512
#define D4    128

// ---------------- device scratch ----------------
__device__ float g_h[(size_t)MAX_N * D];   // h = x @ W (20 MB)
__device__ float g_deg[MAX_N];
__device__ float g_dinv[MAX_N];

// ---------------- degree / normalization ----------------
__global__ void k_deg_init(int n) {
    int i = blockIdx.x * blockDim.x + threadIdx.x;
    if (i < n) g_deg[i] = 1.0f;
}
__global__ void k_deg_acc(const int* __restrict__ ei,
                          const float* __restrict__ ew, int E) {
    int e = blockIdx.x * blockDim.x + threadIdx.x;
    if (e < E) atomicAdd(&g_deg[ei[E + e]], ew[e]);
}
__global__ void k_dinv(int n) {
    int i = blockIdx.x * blockDim.x + threadIdx.x;
    if (i < n) {
        float d = g_deg[i];
        g_dinv[i] = (d > 0.0f) ? rsqrtf(d) : 0.0f;
    }
}

// ---------------- tf32 tensor-core GEMM + fused epilogue ----------------
// h = x@W ; out = b + h * dinv^2
#define BM 128
#define BN 128
#define BK 16
#define KT (D / BK)        // 32 k-tiles
#define AS 20              // As row stride (pad: conflict-free frag loads)
#define BS 136             // Bs row stride (pad: conflict-free frag loads)

__device__ __forceinline__ uint32_t f2tf32(float f) {
    uint32_t r;
    asm("cvt.rna.tf32.f32 %0, %1;" : "=r"(r) : "f"(f));
    return r;
}
__device__ __forceinline__ void mma_tf32(float c[4], const uint32_t a[4],
                                         uint32_t b0, uint32_t b1) {
    asm volatile(
        "mma.sync.aligned.m16n8k8.row.col.f32.tf32.tf32.f32 "
        "{%0,%1,%2,%3}, {%4,%5,%6,%7}, {%8,%9}, {%0,%1,%2,%3};"
        : "+f"(c[0]), "+f"(c[1]), "+f"(c[2]), "+f"(c[3])
        : "r"(a[0]), "r"(a[1]), "r"(a[2]), "r"(a[3]), "r"(b0), "r"(b1));
}
__device__ __forceinline__ void cp16(uint32_t dst, const float* src, int bytes) {
    asm volatile("cp.async.cg.shared.global [%0], [%1], 16, %2;"
                 :: "r"(dst), "l"(src), "r"(bytes));
}

__global__ __launch_bounds__(256)
void k_gemm_tc(const float* __restrict__ A, const float* __restrict__ B,
               const float* __restrict__ bias, float* __restrict__ H,
               float* __restrict__ out, int M) {
    __shared__ float As[2][BM][AS];
    __shared__ float Bs[2][BK][BS];

    const int tid  = threadIdx.x;
    const int warp = tid >> 5, lane = tid & 31;
    const int g = lane >> 2, t = lane & 3;
    const int wy = warp >> 1;              // 0..3 (M dir)
    const int wx = warp & 1;               // 0..1 (N dir)
    const int m_warp = wy * 32;
    const int n_warp = wx * 64;
    const int m0 = blockIdx.y * BM;
    const int n0 = blockIdx.x * BN;

    // chunk mapping for cp.async (2 x 16B per thread per tile)
    const int a_row0 = tid >> 1;                 // thread handles chunks tid, tid+256
    uint32_t sA = (uint32_t)__cvta_generic_to_shared(&As[0][0][0]);
    uint32_t sB = (uint32_t)__cvta_generic_to_shared(&Bs[0][0][0]);

    float acc[2][8][4];
    #pragma unroll
    for (int mf = 0; mf < 2; mf++)
        #pragma unroll
        for (int nf = 0; nf < 8; nf++)
            #pragma unroll
            for (int i = 0; i < 4; i++) acc[mf][nf][i] = 0.0f;

    // tile loader
    auto load_tiles = [&](int k0, int buf) {
        #pragma unroll
        for (int i = 0; i < 2; i++) {
            int c   = tid + i * 256;        // 0..511
            int row = c >> 2;               // 0..127
            int kq  = (c & 3) * 4;          // 0,4,8,12
            int gr  = m0 + row;
            const float* src = A + (size_t)gr * D + k0 + kq;
            uint32_t dst = sA + (uint32_t)(((buf * BM + row) * AS + kq) * 4);
            cp16(dst, src, (gr < M) ? 16 : 0);
        }
        #pragma unroll
        for (int i = 0; i < 2; i++) {
            int c   = tid + i * 256;        // 0..511
            int row = c >> 5;               // 0..15
            int nq  = (c & 31) * 4;         // 0..124
            const float* src = B + (size_t)(k0 + row) * D + n0 + nq;
            uint32_t dst = sB + (uint32_t)(((buf * BK + row) * BS + nq) * 4);
            cp16(dst, src, 16);
        }
    };

    load_tiles(0, 0);
    asm volatile("cp.async.commit_group;");

    for (int kt = 0; kt < KT; kt++) {
        int buf = kt & 1;
        if (kt + 1 < KT) {
            load_tiles((kt + 1) * BK, (kt + 1) & 1);
            asm volatile("cp.async.commit_group;");
            asm volatile("cp.async.wait_group 1;");
        } else {
            asm volatile("cp.async.wait_group 0;");
        }
        __syncthreads();

        #pragma unroll
        for (int ks = 0; ks < 2; ks++) {
            const int kk = ks * 8;
            uint32_t a[2][4];
            #pragma unroll
            for (int mf = 0; mf < 2; mf++) {
                int r = m_warp + mf * 16 + g;
                a[mf][0] = f2tf32(As[buf][r][kk + t]);
                a[mf][1] = f2tf32(As[buf][r + 8][kk + t]);
                a[mf][2] = f2tf32(As[buf][r][kk + t + 4]);
                a[mf][3] = f2tf32(As[buf][r + 8][kk + t + 4]);
            }
            #pragma unroll
            for (int nf = 0; nf < 8; nf++) {
                int ncol = n_warp + nf * 8 + g;
                uint32_t b0 = f2tf32(Bs[buf][kk + t][ncol]);
                uint32_t b1 = f2tf32(Bs[buf][kk + t + 4][ncol]);
                mma_tf32(acc[0][nf], a[0], b0, b1);
                mma_tf32(acc[1][nf], a[1], b0, b1);
            }
        }
        __syncthreads();
    }

    // fused epilogue: H = h ; out = bias + h * dinv^2
    #pragma unroll
    for (int mf = 0; mf < 2; mf++) {
        #pragma unroll
        for (int half = 0; half < 2; half++) {
            int r = m0 + m_warp + mf * 16 + g + half * 8;
            if (r >= M) continue;
            float s = g_dinv[r];
            s = s * s;
            #pragma unroll
            for (int nf = 0; nf < 8; nf++) {
                int col = n0 + n_warp + nf * 8 + t * 2;
                float c0 = acc[mf][nf][half * 2 + 0];
                float c1 = acc[mf][nf][half * 2 + 1];
                float2 bv = *(const float2*)(bias + col);
                *(float2*)(H + (size_t)r * D + col) = make_float2(c0, c1);
                *(float2*)(out + (size_t)r * D + col) =
                    make_float2(bv.x + c0 * s, bv.y + c1 * s);
            }
        }
    }
}

// ---------------- edge scatter: one warp per edge, vector reduces ----------------
__global__ __launch_bounds__(256)
void k_scatter(const int* __restrict__ ei, const float* __restrict__ ew,
               float* __restrict__ out, int E) {
    int w = (int)((blockIdx.x * blockDim.x + threadIdx.x) >> 5);
    int lane = threadIdx.x & 31;
    if (w >= E) return;

    int r = ei[w];        // source
    int c = ei[E + w];    // target
    float nrm = g_dinv[r] * ew[w] * g_dinv[c];

    const float4* hp = (const float4*)g_h + (size_t)r * D4;
    float4* op = (float4*)out + (size_t)c * D4;

    #pragma unroll
    for (int i = 0; i < 4; i++) {
        int idx = lane + i * 32;
        float4 v = hp[idx];
        v.x *= nrm; v.y *= nrm; v.z *= nrm; v.w *= nrm;
        asm volatile("red.global.add.v4.f32 [%0], {%1,%2,%3,%4};"
                     :: "l"(op + idx), "f"(v.x), "f"(v.y), "f"(v.z), "f"(v.w)
                     : "memory");
    }
}

// ---------------- launch ----------------
extern "C" void kernel_launch(void* const* d_in, const int* in_sizes, int n_in,
                              void* d_out, int out_size) {
    const float* x  = (const float*)d_in[0];       // [N, 512]
    const int*   ei = (const int*)d_in[1];         // [2, E] int32
    const float* ew = (const float*)d_in[2];       // [E]
    const float* W  = (const float*)d_in[3];       // [512, 512]
    const float* b  = (const float*)d_in[4];       // [512]
    float* out = (float*)d_out;

    const int N = in_sizes[0] / D;   // 10000
    const int E = in_sizes[2];       // 160000

    float* h;
    cudaGetSymbolAddress((void**)&h, g_h);

    // 1) degree + dinv (must precede GEMM: epilogue reads dinv)
    k_deg_init<<<(N + 255) / 256, 256>>>(N);
    k_deg_acc<<<(E + 255) / 256, 256>>>(ei, ew, E);
    k_dinv<<<(N + 255) / 256, 256>>>(N);

    // 2) h = x @ W  with fused  out = b + h*dinv^2
    dim3 grid(D / BN, (N + BM - 1) / BM);   // (4, 79)
    k_gemm_tc<<<grid, 256>>>(x, W, b, h, out, N);

    // 3) edge scatter with vector global reduces
    int blocks = (E * 32 + 255) / 256;
    k_scatter<<<blocks, 256>>>(ei, ew, out, E);
}

// round 11
// speedup vs baseline: 2.1613x; 1.0727x over previous
#include <cuda_runtime.h>
#include <cstdint>

// GCNConv: N=10000 nodes, E=160000 edges, D_in=D_out=512
#define MAX_N 10000
#define MAX_E 160000
#define D     512
#define D4    128

// ---------------- device scratch ----------------
__device__ float g_h [(size_t)MAX_N * D];   // h = x @ W (20 MB)
__device__ float g_xa[(size_t)MAX_N * D];   // x pre-converted to tf32 bits (20 MB)
__device__ float g_wb[(size_t)D * D];       // W pre-converted to tf32 bits (1 MB)
__device__ float g_deg[MAX_N];
__device__ float g_dinv[MAX_N];
// CSR by target node
__device__ int   g_cnt[MAX_N];
__device__ int   g_rowptr[MAX_N + 1];
__device__ int   g_cursor[MAX_N];
__device__ int   g_src[MAX_E];
__device__ float g_wn[MAX_E];

// ---------------- degree + histogram ----------------
__global__ void k_deg_init(int n) {
    int i = blockIdx.x * blockDim.x + threadIdx.x;
    if (i < n) { g_deg[i] = 1.0f; g_cnt[i] = 0; }
}
__global__ void k_deg_acc(const int* __restrict__ ei,
                          const float* __restrict__ ew, int E) {
    int e = blockIdx.x * blockDim.x + threadIdx.x;
    if (e < E) {
        int c = ei[E + e];
        atomicAdd(&g_deg[c], ew[e]);
        atomicAdd(&g_cnt[c], 1);
    }
}
__global__ void k_dinv(int n) {
    int i = blockIdx.x * blockDim.x + threadIdx.x;
    if (i < n) {
        float d = g_deg[i];
        g_dinv[i] = (d > 0.0f) ? rsqrtf(d) : 0.0f;
    }
}

// ---------------- tf32 pre-conversion ----------------
__device__ __forceinline__ float f2tf32f(float f) {
    uint32_t r;
    asm("cvt.rna.tf32.f32 %0, %1;" : "=r"(r) : "f"(f));
    return __uint_as_float(r);
}
__global__ void k_cvt(const float* __restrict__ src, float* __restrict__ dst,
                      int total4) {
    int t = blockIdx.x * blockDim.x + threadIdx.x;
    if (t >= total4) return;
    float4 v = ((const float4*)src)[t];
    v.x = f2tf32f(v.x); v.y = f2tf32f(v.y);
    v.z = f2tf32f(v.z); v.w = f2tf32f(v.w);
    ((float4*)dst)[t] = v;
}

// ---------------- single-block exclusive scan -> rowptr, cursor ----------------
__global__ void k_scan(int n, int E) {
    __shared__ int s[1024];
    int t = threadIdx.x;
    int per = (n + 1023) >> 10;
    int beg = t * per;
    int end = min(beg + per, n);
    int lsum = 0;
    for (int i = beg; i < end; i++) lsum += g_cnt[i];
    s[t] = lsum;
    __syncthreads();
    #pragma unroll
    for (int off = 1; off < 1024; off <<= 1) {
        int v = (t >= off) ? s[t - off] : 0;
        __syncthreads();
        s[t] += v;
        __syncthreads();
    }
    int pre = (t == 0) ? 0 : s[t - 1];
    for (int i = beg; i < end; i++) {
        g_rowptr[i] = pre;
        g_cursor[i] = pre;
        pre += g_cnt[i];
    }
    if (t == 1023) g_rowptr[n] = E;
}

// ---------------- CSR fill (stores precomputed norm) ----------------
__global__ void k_fill(const int* __restrict__ ei, const float* __restrict__ ew,
                       int E) {
    int e = blockIdx.x * blockDim.x + threadIdx.x;
    if (e >= E) return;
    int r = ei[e];
    int c = ei[E + e];
    int pos = atomicAdd(&g_cursor[c], 1);
    g_src[pos] = r;
    g_wn[pos]  = g_dinv[r] * ew[e] * g_dinv[c];
}

// ---------------- tf32 tensor-core GEMM (writes H only) ----------------
#define BM 128
#define BN 128
#define BK 16
#define KT (D / BK)
#define AS 20
#define BS 136

__device__ __forceinline__ void mma_tf32(float c[4], const uint32_t a[4],
                                         uint32_t b0, uint32_t b1) {
    asm volatile(
        "mma.sync.aligned.m16n8k8.row.col.f32.tf32.tf32.f32 "
        "{%0,%1,%2,%3}, {%4,%5,%6,%7}, {%8,%9}, {%0,%1,%2,%3};"
        : "+f"(c[0]), "+f"(c[1]), "+f"(c[2]), "+f"(c[3])
        : "r"(a[0]), "r"(a[1]), "r"(a[2]), "r"(a[3]), "r"(b0), "r"(b1));
}
__device__ __forceinline__ void cp16(uint32_t dst, const float* src, int bytes) {
    asm volatile("cp.async.cg.shared.global [%0], [%1], 16, %2;"
                 :: "r"(dst), "l"(src), "r"(bytes));
}

__global__ __launch_bounds__(256)
void k_gemm_tc(const float* __restrict__ A, const float* __restrict__ B,
               float* __restrict__ H, int M) {
    __shared__ float As[2][BM][AS];
    __shared__ float Bs[2][BK][BS];

    const int tid  = threadIdx.x;
    const int warp = tid >> 5, lane = tid & 31;
    const int g = lane >> 2, t = lane & 3;
    const int wy = warp >> 1;
    const int wx = warp & 1;
    const int m_warp = wy * 32;
    const int n_warp = wx * 64;
    const int m0 = blockIdx.y * BM;
    const int n0 = blockIdx.x * BN;

    uint32_t sA = (uint32_t)__cvta_generic_to_shared(&As[0][0][0]);
    uint32_t sB = (uint32_t)__cvta_generic_to_shared(&Bs[0][0][0]);

    float acc[2][8][4];
    #pragma unroll
    for (int mf = 0; mf < 2; mf++)
        #pragma unroll
        for (int nf = 0; nf < 8; nf++)
            #pragma unroll
            for (int i = 0; i < 4; i++) acc[mf][nf][i] = 0.0f;

    auto load_tiles = [&](int k0, int buf) {
        #pragma unroll
        for (int i = 0; i < 2; i++) {
            int c   = tid + i * 256;
            int row = c >> 2;
            int kq  = (c & 3) * 4;
            int gr  = m0 + row;
            const float* src = A + (size_t)gr * D + k0 + kq;
            uint32_t dst = sA + (uint32_t)(((buf * BM + row) * AS + kq) * 4);
            cp16(dst, src, (gr < M) ? 16 : 0);
        }
        #pragma unroll
        for (int i = 0; i < 2; i++) {
            int c   = tid + i * 256;
            int row = c >> 5;
            int nq  = (c & 31) * 4;
            const float* src = B + (size_t)(k0 + row) * D + n0 + nq;
            uint32_t dst = sB + (uint32_t)(((buf * BK + row) * BS + nq) * 4);
            cp16(dst, src, 16);
        }
    };

    load_tiles(0, 0);
    asm volatile("cp.async.commit_group;");

    for (int kt = 0; kt < KT; kt++) {
        int buf = kt & 1;
        if (kt + 1 < KT) {
            load_tiles((kt + 1) * BK, (kt + 1) & 1);
            asm volatile("cp.async.commit_group;");
            asm volatile("cp.async.wait_group 1;");
        } else {
            asm volatile("cp.async.wait_group 0;");
        }
        __syncthreads();

        #pragma unroll
        for (int ks = 0; ks < 2; ks++) {
            const int kk = ks * 8;
            uint32_t a[2][4];
            #pragma unroll
            for (int mf = 0; mf < 2; mf++) {
                int r = m_warp + mf * 16 + g;
                a[mf][0] = __float_as_uint(As[buf][r][kk + t]);
                a[mf][1] = __float_as_uint(As[buf][r + 8][kk + t]);
                a[mf][2] = __float_as_uint(As[buf][r][kk + t + 4]);
                a[mf][3] = __float_as_uint(As[buf][r + 8][kk + t + 4]);
            }
            #pragma unroll
            for (int nf = 0; nf < 8; nf++) {
                int ncol = n_warp + nf * 8 + g;
                uint32_t b0 = __float_as_uint(Bs[buf][kk + t][ncol]);
                uint32_t b1 = __float_as_uint(Bs[buf][kk + t + 4][ncol]);
                mma_tf32(acc[0][nf], a[0], b0, b1);
                mma_tf32(acc[1][nf], a[1], b0, b1);
            }
        }
        __syncthreads();
    }

    #pragma unroll
    for (int mf = 0; mf < 2; mf++) {
        #pragma unroll
        for (int half = 0; half < 2; half++) {
            int r = m0 + m_warp + mf * 16 + g + half * 8;
            if (r >= M) continue;
            #pragma unroll
            for (int nf = 0; nf < 8; nf++) {
                int col = n0 + n_warp + nf * 8 + t * 2;
                *(float2*)(H + (size_t)r * D + col) =
                    make_float2(acc[mf][nf][half * 2 + 0],
                                acc[mf][nf][half * 2 + 1]);
            }
        }
    }
}

// ---------------- gather: one warp per target node ----------------
__global__ __launch_bounds__(256)
void k_gather(const float* __restrict__ bias, float* __restrict__ out, int n) {
    int w = (int)((blockIdx.x * blockDim.x + threadIdx.x) >> 5);
    int lane = threadIdx.x & 31;
    if (w >= n) return;

    int rs = g_rowptr[w];
    int re = g_rowptr[w + 1];
    float s = g_dinv[w];
    s = s * s;

    const float4* hp = (const float4*)g_h;
    const float4* bp = (const float4*)bias;

    float4 acc[4];
    #pragma unroll
    for (int i = 0; i < 4; i++) {
        int idx = lane + i * 32;
        float4 bv = bp[idx];
        float4 hv = hp[(size_t)w * D4 + idx];
        acc[i].x = bv.x + hv.x * s;
        acc[i].y = bv.y + hv.y * s;
        acc[i].z = bv.z + hv.z * s;
        acc[i].w = bv.w + hv.w * s;
    }

    for (int e = rs; e < re; e++) {
        int r = g_src[e];
        float nrm = g_wn[e];
        const float4* rp = hp + (size_t)r * D4;
        #pragma unroll
        for (int i = 0; i < 4; i++) {
            float4 v = rp[lane + i * 32];
            acc[i].x = fmaf(v.x, nrm, acc[i].x);
            acc[i].y = fmaf(v.y, nrm, acc[i].y);
            acc[i].z = fmaf(v.z, nrm, acc[i].z);
            acc[i].w = fmaf(v.w, nrm, acc[i].w);
        }
    }

    float4* op = (float4*)out + (size_t)w * D4;
    #pragma unroll
    for (int i = 0; i < 4; i++) op[lane + i * 32] = acc[i];
}

// ---------------- launch ----------------
extern "C" void kernel_launch(void* const* d_in, const int* in_sizes, int n_in,
                              void* d_out, int out_size) {
    const float* x  = (const float*)d_in[0];       // [N, 512]
    const int*   ei = (const int*)d_in[1];         // [2, E] int32
    const float* ew = (const float*)d_in[2];       // [E]
    const float* W  = (const float*)d_in[3];       // [512, 512]
    const float* b  = (const float*)d_in[4];       // [512]
    float* out = (float*)d_out;

    const int N = in_sizes[0] / D;   // 10000
    const int E = in_sizes[2];       // 160000

    float *h, *xa, *wb;
    cudaGetSymbolAddress((void**)&h,  g_h);
    cudaGetSymbolAddress((void**)&xa, g_xa);
    cudaGetSymbolAddress((void**)&wb, g_wb);

    // 1) degree + histogram + dinv
    k_deg_init<<<(N + 255) / 256, 256>>>(N);
    k_deg_acc<<<(E + 255) / 256, 256>>>(ei, ew, E);
    k_dinv<<<(N + 255) / 256, 256>>>(N);

    // 2) tf32 pre-conversion of x and W
    int x4 = N * D / 4, w4 = D * D / 4;
    k_cvt<<<(x4 + 255) / 256, 256>>>(x, xa, x4);
    k_cvt<<<(w4 + 255) / 256, 256>>>(W, wb, w4);

    // 3) h = x @ W (tensor cores, cvt-free mainloop)
    dim3 grid(D / BN, (N + BM - 1) / BM);
    k_gemm_tc<<<grid, 256>>>(xa, wb, h, N);

    // 4) CSR build (scan + fill; fill needs dinv, done above)
    k_scan<<<1, 1024>>>(N, E);
    k_fill<<<(E + 255) / 256, 256>>>(ei, ew, E);

    // 5) gather: out = b + h[c]*dinv^2 + sum_e norm * h[src]
    int blocks = (N * 32 + 255) / 256;
    k_gather<<<blocks, 256>>>(b, out, N);
}

// round 13
// speedup vs baseline: 2.4960x; 1.1549x over previous
#include <cuda_runtime.h>
#include <cstdint>

// GCNConv: N=10000 nodes, E=160000 edges, D_in=D_out=512
#define MAX_N 10000
#define MAX_E 160000
#define D     512
#define D4    128

// ---------------- device scratch ----------------
__device__ float g_h [(size_t)MAX_N * D];   // h = x @ W (20 MB)
__device__ float g_wb[(size_t)D * D];       // W pre-converted to tf32 bits (1 MB)
__device__ float g_deg[MAX_N];
__device__ float g_dinv[MAX_N];
// CSR by target node
__device__ int   g_cnt[MAX_N];
__device__ int   g_rowptr[MAX_N + 1];
__device__ int   g_cursor[MAX_N];
__device__ int   g_src[MAX_E];
__device__ float g_wn[MAX_E];

// ---------------- degree + histogram ----------------
__global__ void k_deg_init(int n) {
    int i = blockIdx.x * blockDim.x + threadIdx.x;
    if (i < n) { g_deg[i] = 1.0f; g_cnt[i] = 0; }
}
__global__ void k_deg_acc(const int* __restrict__ ei,
                          const float* __restrict__ ew, int E) {
    int e = blockIdx.x * blockDim.x + threadIdx.x;
    if (e < E) {
        int c = ei[E + e];
        atomicAdd(&g_deg[c], ew[e]);
        atomicAdd(&g_cnt[c], 1);
    }
}
__global__ void k_dinv(int n) {
    int i = blockIdx.x * blockDim.x + threadIdx.x;
    if (i < n) {
        float d = g_deg[i];
        g_dinv[i] = (d > 0.0f) ? rsqrtf(d) : 0.0f;
    }
}

// ---------------- tf32 pre-conversion (W only) ----------------
__device__ __forceinline__ float f2tf32f(float f) {
    uint32_t r;
    asm("cvt.rna.tf32.f32 %0, %1;" : "=r"(r) : "f"(f));
    return __uint_as_float(r);
}
__global__ void k_cvt(const float* __restrict__ src, float* __restrict__ dst,
                      int total4) {
    int t = blockIdx.x * blockDim.x + threadIdx.x;
    if (t >= total4) return;
    float4 v = ((const float4*)src)[t];
    v.x = f2tf32f(v.x); v.y = f2tf32f(v.y);
    v.z = f2tf32f(v.z); v.w = f2tf32f(v.w);
    ((float4*)dst)[t] = v;
}

// ---------------- single-block exclusive scan -> rowptr, cursor ----------------
__global__ void k_scan(int n, int E) {
    __shared__ int s[1024];
    int t = threadIdx.x;
    int per = (n + 1023) >> 10;
    int beg = t * per;
    int end = min(beg + per, n);
    int lsum = 0;
    for (int i = beg; i < end; i++) lsum += g_cnt[i];
    s[t] = lsum;
    __syncthreads();
    #pragma unroll
    for (int off = 1; off < 1024; off <<= 1) {
        int v = (t >= off) ? s[t - off] : 0;
        __syncthreads();
        s[t] += v;
        __syncthreads();
    }
    int pre = (t == 0) ? 0 : s[t - 1];
    for (int i = beg; i < end; i++) {
        g_rowptr[i] = pre;
        g_cursor[i] = pre;
        pre += g_cnt[i];
    }
    if (t == 1023) g_rowptr[n] = E;
}

// ---------------- CSR fill (stores precomputed norm) ----------------
__global__ void k_fill(const int* __restrict__ ei, const float* __restrict__ ew,
                       int E) {
    int e = blockIdx.x * blockDim.x + threadIdx.x;
    if (e >= E) return;
    int r = ei[e];
    int c = ei[E + e];
    int pos = atomicAdd(&g_cursor[c], 1);
    g_src[pos] = r;
    g_wn[pos]  = g_dinv[r] * ew[e] * g_dinv[c];
}

// ---------------- tf32 tensor-core GEMM, 64x64 warp tiles ----------------
// A = raw fp32 x (HW truncates to tf32); B = rna-converted W.
#define BM 128
#define BN 128
#define BK 16
#define KT (D / BK)
#define AS 20
#define BS 136

__device__ __forceinline__ void mma_tf32(float c[4], const uint32_t a[4],
                                         uint32_t b0, uint32_t b1) {
    asm volatile(
        "mma.sync.aligned.m16n8k8.row.col.f32.tf32.tf32.f32 "
        "{%0,%1,%2,%3}, {%4,%5,%6,%7}, {%8,%9}, {%0,%1,%2,%3};"
        : "+f"(c[0]), "+f"(c[1]), "+f"(c[2]), "+f"(c[3])
        : "r"(a[0]), "r"(a[1]), "r"(a[2]), "r"(a[3]), "r"(b0), "r"(b1));
}
__device__ __forceinline__ void cp16(uint32_t dst, const float* src, int bytes) {
    asm volatile("cp.async.cg.shared.global [%0], [%1], 16, %2;"
                 :: "r"(dst), "l"(src), "r"(bytes));
}

__global__ __launch_bounds__(128, 2)
void k_gemm_tc(const float* __restrict__ A, const float* __restrict__ B,
               float* __restrict__ H, int M) {
    __shared__ float As[2][BM][AS];
    __shared__ float Bs[2][BK][BS];

    const int tid  = threadIdx.x;
    const int warp = tid >> 5, lane = tid & 31;
    const int g = lane >> 2, t = lane & 3;
    const int wy = warp >> 1;              // 0..1 (M dir)
    const int wx = warp & 1;               // 0..1 (N dir)
    const int m_warp = wy * 64;
    const int n_warp = wx * 64;
    const int m0 = blockIdx.y * BM;
    const int n0 = blockIdx.x * BN;

    uint32_t sA = (uint32_t)__cvta_generic_to_shared(&As[0][0][0]);
    uint32_t sB = (uint32_t)__cvta_generic_to_shared(&Bs[0][0][0]);

    float acc[4][8][4];
    #pragma unroll
    for (int mf = 0; mf < 4; mf++)
        #pragma unroll
        for (int nf = 0; nf < 8; nf++)
            #pragma unroll
            for (int i = 0; i < 4; i++) acc[mf][nf][i] = 0.0f;

    // 128 threads: 4 x 16B chunks each for A (8KB) and B (8KB)
    auto load_tiles = [&](int k0, int buf) {
        #pragma unroll
        for (int i = 0; i < 4; i++) {
            int c   = tid + i * 128;        // 0..511
            int row = c >> 2;               // 0..127
            int kq  = (c & 3) * 4;          // 0,4,8,12
            int gr  = m0 + row;
            const float* src = A + (size_t)gr * D + k0 + kq;
            uint32_t dst = sA + (uint32_t)(((buf * BM + row) * AS + kq) * 4);
            cp16(dst, src, (gr < M) ? 16 : 0);
        }
        #pragma unroll
        for (int i = 0; i < 4; i++) {
            int c   = tid + i * 128;        // 0..511
            int row = c >> 5;               // 0..15
            int nq  = (c & 31) * 4;         // 0..124
            const float* src = B + (size_t)(k0 + row) * D + n0 + nq;
            uint32_t dst = sB + (uint32_t)(((buf * BK + row) * BS + nq) * 4);
            cp16(dst, src, 16);
        }
    };

    load_tiles(0, 0);
    asm volatile("cp.async.commit_group;");

    for (int kt = 0; kt < KT; kt++) {
        int buf = kt & 1;
        if (kt + 1 < KT) {
            load_tiles((kt + 1) * BK, (kt + 1) & 1);
            asm volatile("cp.async.commit_group;");
            asm volatile("cp.async.wait_group 1;");
        } else {
            asm volatile("cp.async.wait_group 0;");
        }
        __syncthreads();

        #pragma unroll
        for (int ks = 0; ks < 2; ks++) {
            const int kk = ks * 8;
            uint32_t a[4][4];
            #pragma unroll
            for (int mf = 0; mf < 4; mf++) {
                int r = m_warp + mf * 16 + g;
                a[mf][0] = __float_as_uint(As[buf][r][kk + t]);
                a[mf][1] = __float_as_uint(As[buf][r + 8][kk + t]);
                a[mf][2] = __float_as_uint(As[buf][r][kk + t + 4]);
                a[mf][3] = __float_as_uint(As[buf][r + 8][kk + t + 4]);
            }
            #pragma unroll
            for (int nf = 0; nf < 8; nf++) {
                int ncol = n_warp + nf * 8 + g;
                uint32_t b0 = __float_as_uint(Bs[buf][kk + t][ncol]);
                uint32_t b1 = __float_as_uint(Bs[buf][kk + t + 4][ncol]);
                #pragma unroll
                for (int mf = 0; mf < 4; mf++)
                    mma_tf32(acc[mf][nf], a[mf], b0, b1);
            }
        }
        __syncthreads();
    }

    #pragma unroll
    for (int mf = 0; mf < 4; mf++) {
        #pragma unroll
        for (int half = 0; half < 2; half++) {
            int r = m0 + m_warp + mf * 16 + g + half * 8;
            if (r >= M) continue;
            #pragma unroll
            for (int nf = 0; nf < 8; nf++) {
                int col = n0 + n_warp + nf * 8 + t * 2;
                *(float2*)(H + (size_t)r * D + col) =
                    make_float2(acc[mf][nf][half * 2 + 0],
                                acc[mf][nf][half * 2 + 1]);
            }
        }
    }
}

// ---------------- gather: one warp per target node ----------------
__global__ __launch_bounds__(256)
void k_gather(const float* __restrict__ bias, float* __restrict__ out, int n) {
    int w = (int)((blockIdx.x * blockDim.x + threadIdx.x) >> 5);
    int lane = threadIdx.x & 31;
    if (w >= n) return;

    int rs = g_rowptr[w];
    int re = g_rowptr[w + 1];
    float s = g_dinv[w];
    s = s * s;

    const float4* hp = (const float4*)g_h;
    const float4* bp = (const float4*)bias;

    float4 acc[4];
    #pragma unroll
    for (int i = 0; i < 4; i++) {
        int idx = lane + i * 32;
        float4 bv = bp[idx];
        float4 hv = hp[(size_t)w * D4 + idx];
        acc[i].x = bv.x + hv.x * s;
        acc[i].y = bv.y + hv.y * s;
        acc[i].z = bv.z + hv.z * s;
        acc[i].w = bv.w + hv.w * s;
    }

    for (int e = rs; e < re; e++) {
        int r = g_src[e];
        float nrm = g_wn[e];
        const float4* rp = hp + (size_t)r * D4;
        #pragma unroll
        for (int i = 0; i < 4; i++) {
            float4 v = rp[lane + i * 32];
            acc[i].x = fmaf(v.x, nrm, acc[i].x);
            acc[i].y = fmaf(v.y, nrm, acc[i].y);
            acc[i].z = fmaf(v.z, nrm, acc[i].z);
            acc[i].w = fmaf(v.w, nrm, acc[i].w);
        }
    }

    float4* op = (float4*)out + (size_t)w * D4;
    #pragma unroll
    for (int i = 0; i < 4; i++) op[lane + i * 32] = acc[i];
}

// ---------------- launch ----------------
extern "C" void kernel_launch(void* const* d_in, const int* in_sizes, int n_in,
                              void* d_out, int out_size) {
    const float* x  = (const float*)d_in[0];       // [N, 512]
    const int*   ei = (const int*)d_in[1];         // [2, E] int32
    const float* ew = (const float*)d_in[2];       // [E]
    const float* W  = (const float*)d_in[3];       // [512, 512]
    const float* b  = (const float*)d_in[4];       // [512]
    float* out = (float*)d_out;

    const int N = in_sizes[0] / D;   // 10000
    const int E = in_sizes[2];       // 160000

    float *h, *wb;
    cudaGetSymbolAddress((void**)&h,  g_h);
    cudaGetSymbolAddress((void**)&wb, g_wb);

    // 1) degree + histogram + dinv
    k_deg_init<<<(N + 255) / 256, 256>>>(N);
    k_deg_acc<<<(E + 255) / 256, 256>>>(ei, ew, E);
    k_dinv<<<(N + 255) / 256, 256>>>(N);

    // 2) tf32 pre-conversion of W only (x fed raw: HW truncates to tf32)
    int w4 = D * D / 4;
    k_cvt<<<(w4 + 255) / 256, 256>>>(W, wb, w4);

    // 3) h = x @ W (tensor cores, 64x64 warp tiles)
    dim3 grid(D / BN, (N + BM - 1) / BM);   // (4, 79)
    k_gemm_tc<<<grid, 128>>>(x, wb, h, N);

    // 4) CSR build
    k_scan<<<1, 1024>>>(N, E);
    k_fill<<<(E + 255) / 256, 256>>>(ei, ew, E);

    // 5) gather: out = b + h[c]*dinv^2 + sum_e norm * h[src]
    int blocks = (N * 32 + 255) / 256;
    k_gather<<<blocks, 256>>>(b, out, N);
}